// round 5
// baseline (speedup 1.0000x reference)
#include <cuda_runtime.h>
#include <cstdint>
#include <math.h>

#define B_SZ 16384
#define H_SZ 512
#define G4   2048
#define OUTF 256
#define KPAD 288
#define IN0  257
#define MB   128          // row-blocks along batch = B/128

// ---------------- scratch (static device memory) ------------------------------
__device__ float g_inp [(size_t)B_SZ * KPAD];   // tf32, k-permuted concat(x,y) padded
__device__ float g_WxP [(size_t)G4 * KPAD];
__device__ float g_Zx  [(size_t)B_SZ * G4];
__device__ float g_Zh  [(size_t)B_SZ * G4];
__device__ float g_h00t[(size_t)B_SZ * H_SZ];
__device__ float g_h01t[(size_t)B_SZ * H_SZ];
__device__ float g_h1t [(size_t)B_SZ * H_SZ];
__device__ float g_h2t [(size_t)B_SZ * H_SZ];
__device__ float g_Wh0t[(size_t)G4 * H_SZ];
__device__ float g_Wx1t[(size_t)G4 * H_SZ];
__device__ float g_Wh1t[(size_t)G4 * H_SZ];
__device__ float g_Wot [(size_t)OUTF * H_SZ];
__device__ float g_partX[(size_t)MB * G4 * 2];
__device__ float g_partH[(size_t)MB * G4 * 2];
__device__ float g_scX[G4], g_shX[G4], g_scH[G4], g_shH[G4];

// ---------------- helpers ------------------------------------------------------
__device__ __forceinline__ uint32_t f2tf(float f) {
    uint32_t u = __float_as_uint(f);
    uint32_t r = u + 0xFFFu + ((u >> 13) & 1u);   // RNE to tf32
    return r & 0xFFFFE000u;
}
__device__ __forceinline__ float tf(float f) { return __uint_as_float(f2tf(f)); }
__device__ __forceinline__ float sigm(float x) { return 1.f / (1.f + expf(-x)); }

// per-8-group permutation: physical p holds logical k(p) = (p>>1) + ((p&1)<<2)
// i.e. dst = {s0,s4,s1,s5,s2,s6,s3,s7}

// ---------------- vectorized prep kernels (one thread per 8-group) -------------
__global__ void prep_inp(const float* __restrict__ x, const float* __restrict__ y) {
    int t = blockIdx.x * blockDim.x + threadIdx.x;     // B * 36 groups
    if (t >= B_SZ * (KPAD / 8)) return;
    int b = t / (KPAD / 8), gi = t - b * (KPAD / 8);
    int j0 = gi * 8;
    float s[8];
#pragma unroll
    for (int i = 0; i < 8; i++) {
        int j = j0 + i;
        s[i] = (j < 256) ? x[(size_t)b * 256 + j] : (j == IN0 - 1 ? y[b] : 0.f);
    }
    float4 d0 = make_float4(tf(s[0]), tf(s[4]), tf(s[1]), tf(s[5]));
    float4 d1 = make_float4(tf(s[2]), tf(s[6]), tf(s[3]), tf(s[7]));
    float4* dst = (float4*)(g_inp + (size_t)b * KPAD + j0);
    dst[0] = d0; dst[1] = d1;
}
__global__ void prep_wx(const float* __restrict__ Wx) {
    int t = blockIdx.x * blockDim.x + threadIdx.x;     // G4 * 36 groups
    if (t >= G4 * (KPAD / 8)) return;
    int r = t / (KPAD / 8), gi = t - r * (KPAD / 8);
    int j0 = gi * 8;
    float s[8];
#pragma unroll
    for (int i = 0; i < 8; i++) {
        int j = j0 + i;
        s[i] = (j < IN0) ? Wx[(size_t)r * IN0 + j] : 0.f;
    }
    float4 d0 = make_float4(tf(s[0]), tf(s[4]), tf(s[1]), tf(s[5]));
    float4 d1 = make_float4(tf(s[2]), tf(s[6]), tf(s[3]), tf(s[7]));
    float4* dst = (float4*)(g_WxP + (size_t)r * KPAD + j0);
    dst[0] = d0; dst[1] = d1;
}
__global__ void conv_perm(float* __restrict__ dst, const float* __restrict__ src, int n8) {
    int t = blockIdx.x * blockDim.x + threadIdx.x;     // n/8 threads
    if (t >= n8) return;
    const float4* sp = (const float4*)(src + (size_t)t * 8);
    float4 s0 = sp[0], s1 = sp[1];
    float4 d0 = make_float4(tf(s0.x), tf(s1.x), tf(s0.y), tf(s1.y));
    float4 d1 = make_float4(tf(s0.z), tf(s1.z), tf(s0.w), tf(s1.w));
    float4* dp = (float4*)(dst + (size_t)t * 8);
    dp[0] = d0; dp[1] = d1;
}

// ---------------- tf32 mma GEMM: C[M,N] = A[M,K] * W[N,K]^T (+bias) ------------
// block 128x128, BK=32, 8 warps (2x4), warp tile 64x32, cp.async double buffer.
// smem layout per kb quadrant (8 k-floats per row, permuted pairs):
//   float offset = (r>>2)*32 + (r&3)*8 + u   -> conflict-free LDS.64 fragments
constexpr int BM = 128, BN = 128, BK = 32;
constexpr int QUAD = BM * 8;                 // 1024 floats per quadrant
constexpr int STG = (BM + BN) * BK;          // 8192 floats per stage (32 KB)

__device__ __forceinline__ void cpasync16(uint32_t dst, const void* src) {
    asm volatile("cp.async.cg.shared.global [%0], [%1], 16;\n" :: "r"(dst), "l"(src));
}
__device__ __forceinline__ int sidx(int r, int u) {
    return ((r >> 2) << 5) + ((r & 3) << 3) + u;
}

__global__ __launch_bounds__(256, 2) void gemm_tn(
    float* __restrict__ C, const float* __restrict__ A, int lda,
    const float* __restrict__ W, int ldw, int N, int K,
    const float* __restrict__ bias, float* __restrict__ part)
{
    extern __shared__ float sm[];
    const int tid  = threadIdx.x;
    const int lane = tid & 31, warp = tid >> 5;
    const int g    = lane >> 2, tg = lane & 3;
    const int wm   = warp >> 2, wn = warp & 3;          // 2 x 4 warps
    const int mW   = wm * 64, nW = wn * 32;             // warp tile 64x32
    const int bM   = blockIdx.y * BM, bN = blockIdx.x * BN;
    const uint32_t smB = (uint32_t)__cvta_generic_to_shared(sm);

    float acc[4][4][4];
#pragma unroll
    for (int a = 0; a < 4; a++)
#pragma unroll
        for (int b = 0; b < 4; b++)
#pragma unroll
            for (int c = 0; c < 4; c++) acc[a][b][c] = 0.f;

    auto load_stage = [&](int st, int k0) {
        uint32_t base = smB + (uint32_t)(st * STG) * 4u;
#pragma unroll
        for (int i = 0; i < 4; i++) {                  // A tile 128x32 = 1024 float4
            int u = tid + i * 256, row = u >> 3, ch = u & 7;
            int kb = ch >> 1, half = ch & 1;
            const float* src = A + (size_t)(bM + row) * lda + k0 + ch * 4;
            uint32_t dst = base + (uint32_t)(kb * QUAD + sidx(row, half * 4)) * 4u;
            cpasync16(dst, src);
        }
#pragma unroll
        for (int i = 0; i < 4; i++) {                  // W tile 128x32
            int u = tid + i * 256, row = u >> 3, ch = u & 7;
            int kb = ch >> 1, half = ch & 1;
            const float* src = W + (size_t)(bN + row) * ldw + k0 + ch * 4;
            uint32_t dst = base + (uint32_t)(BM * BK + kb * QUAD + sidx(row, half * 4)) * 4u;
            cpasync16(dst, src);
        }
    };

    auto compute = [&](int st) {
        const float* sA = sm + st * STG;
        const float* sW = sm + st * STG + BM * BK;
#pragma unroll
        for (int kb = 0; kb < 4; kb++) {
            uint2 bf[4];
#pragma unroll
            for (int nt = 0; nt < 4; nt++)
                bf[nt] = *(const uint2*)&sW[kb * QUAD + sidx(nW + nt * 8 + g, 2 * tg)];
            uint2 a02[4], a13[4];
#pragma unroll
            for (int mt = 0; mt < 4; mt++) {
                int r0 = mW + mt * 16 + g;
                a02[mt] = *(const uint2*)&sA[kb * QUAD + sidx(r0,     2 * tg)];
                a13[mt] = *(const uint2*)&sA[kb * QUAD + sidx(r0 + 8, 2 * tg)];
            }
#pragma unroll
            for (int mt = 0; mt < 4; mt++)
#pragma unroll
                for (int nt = 0; nt < 4; nt++)
                    asm volatile(
                        "mma.sync.aligned.m16n8k8.row.col.f32.tf32.tf32.f32 "
                        "{%0,%1,%2,%3},{%4,%5,%6,%7},{%8,%9},{%0,%1,%2,%3};\n"
                        : "+f"(acc[mt][nt][0]), "+f"(acc[mt][nt][1]),
                          "+f"(acc[mt][nt][2]), "+f"(acc[mt][nt][3])
                        : "r"(a02[mt].x), "r"(a13[mt].x), "r"(a02[mt].y), "r"(a13[mt].y),
                          "r"(bf[nt].x), "r"(bf[nt].y));
        }
    };

    const int nit = K >> 5;
    load_stage(0, 0);
    asm volatile("cp.async.commit_group;\n");
    for (int it = 0; it < nit; ++it) {
        if (it + 1 < nit) {
            load_stage((it + 1) & 1, (it + 1) << 5);
            asm volatile("cp.async.commit_group;\n");
            asm volatile("cp.async.wait_group 1;\n");
        } else {
            asm volatile("cp.async.wait_group 0;\n");
        }
        __syncthreads();
        compute(it & 1);
        __syncthreads();
    }

    // ---- write C tile ----
#pragma unroll
    for (int mt = 0; mt < 4; mt++) {
        int r0 = bM + mW + mt * 16 + g;
#pragma unroll
        for (int nt = 0; nt < 4; nt++) {
            int c = bN + nW + nt * 8 + 2 * tg;
            float b0 = 0.f, b1 = 0.f;
            if (bias) { b0 = bias[c]; b1 = bias[c + 1]; }
            *(float2*)&C[(size_t)r0 * N + c]       = make_float2(acc[mt][nt][0] + b0, acc[mt][nt][1] + b1);
            *(float2*)&C[(size_t)(r0 + 8) * N + c] = make_float2(acc[mt][nt][2] + b0, acc[mt][nt][3] + b1);
        }
    }

    // ---- fused BN statistics: per-block column (sum, sumsq) partials ----
    if (part) {
        __syncthreads();
        float* psm = sm;                    // [2 wm][128 col][2]
#pragma unroll
        for (int nt = 0; nt < 4; nt++) {
            float s0 = 0.f, q0 = 0.f, s1 = 0.f, q1 = 0.f;
#pragma unroll
            for (int mt = 0; mt < 4; mt++) {
                float v0 = acc[mt][nt][0], v2 = acc[mt][nt][2];
                float v1 = acc[mt][nt][1], v3 = acc[mt][nt][3];
                s0 += v0 + v2; q0 += v0 * v0 + v2 * v2;
                s1 += v1 + v3; q1 += v1 * v1 + v3 * v3;
            }
#pragma unroll
            for (int off = 16; off >= 4; off >>= 1) {
                s0 += __shfl_xor_sync(0xFFFFFFFFu, s0, off);
                q0 += __shfl_xor_sync(0xFFFFFFFFu, q0, off);
                s1 += __shfl_xor_sync(0xFFFFFFFFu, s1, off);
                q1 += __shfl_xor_sync(0xFFFFFFFFu, q1, off);
            }
            if (g == 0) {
                int col = nW + nt * 8 + 2 * tg;
                psm[(wm * 128 + col) * 2 + 0]     = s0;
                psm[(wm * 128 + col) * 2 + 1]     = q0;
                psm[(wm * 128 + col + 1) * 2 + 0] = s1;
                psm[(wm * 128 + col + 1) * 2 + 1] = q1;
            }
        }
        __syncthreads();
        {   // 256 threads fold 2 wm halves -> 128 cols x {s,q}
            int col = tid >> 1, sq = tid & 1;
            float v = psm[col * 2 + sq] + psm[(128 + col) * 2 + sq];
            part[((size_t)blockIdx.y * N + bN + col) * 2 + sq] = v;
        }
    }
}

// ---------------- fold partials into BN affine scale/shift ---------------------
__global__ void stats_final(const float* __restrict__ gx, const float* __restrict__ bx,
                            const float* __restrict__ gh, const float* __restrict__ bh) {
    int j = blockIdx.x * blockDim.x + threadIdx.x;     // 2048
    float sx = 0.f, qx = 0.f, sh = 0.f, qh = 0.f;
    for (int rb = 0; rb < MB; rb++) {
        size_t o = ((size_t)rb * G4 + j) * 2;
        sx += g_partX[o]; qx += g_partX[o + 1];
        sh += g_partH[o]; qh += g_partH[o + 1];
    }
    const float invB = 1.f / (float)B_SZ;
    float mx = sx * invB, vx = qx * invB - mx * mx;
    float ax = gx[j] * rsqrtf(vx + 1e-5f);
    g_scX[j] = ax; g_shX[j] = bx[j] - mx * ax;
    float mh = sh * invB, vh = qh * invB - mh * mh;
    float ah = gh[j] * rsqrtf(vh + 1e-5f);
    g_scH[j] = ah; g_shH[j] = bh[j] - mh * ah;
}

// ---------------- fused BN + LSTM cell + tf32/perm h export --------------------
// one thread per 4 consecutive hidden units
__global__ void cell_kernel(const float* __restrict__ Zx, const float* __restrict__ Zh,
                            const float* __restrict__ cPrev,
                            float* __restrict__ hOut, float* __restrict__ hT,
                            float* __restrict__ cOut) {
    int t = blockIdx.x * blockDim.x + threadIdx.x;     // B*128 threads
    int jv = t & 127, b = t >> 7;                      // jv: float4 index in 512
    size_t base4 = ((size_t)b << 9) + jv;              // float4 units of row (2048/4)
    const float4* zx = (const float4*)Zx;
    const float4* zh = (const float4*)Zh;
    float4 zf4 = zx[base4      ], hf4 = zh[base4      ];
    float4 zi4 = zx[base4 + 128], hi4 = zh[base4 + 128];
    float4 zo4 = zx[base4 + 256], ho4 = zh[base4 + 256];
    float4 zg4 = zx[base4 + 384], hg4 = zh[base4 + 384];
    const float4* scX = (const float4*)g_scX; const float4* shX = (const float4*)g_shX;
    const float4* scH = (const float4*)g_scH; const float4* shH = (const float4*)g_shH;
    float4 sxf = scX[jv], txf = shX[jv], shf = scH[jv], thf = shH[jv];
    float4 sxi = scX[jv + 128], txi = shX[jv + 128], shi = scH[jv + 128], thi = shH[jv + 128];
    float4 sxo = scX[jv + 256], txo = shX[jv + 256], sho = scH[jv + 256], tho = shH[jv + 256];
    float4 sxg = scX[jv + 384], txg = shX[jv + 384], shg = scH[jv + 384], thg = shH[jv + 384];
    float4 cp = ((const float4*)cPrev)[((size_t)b << 7) + jv];

    float h[4], c[4];
    {
        float zf[4] = { zf4.x*sxf.x+txf.x + hf4.x*shf.x+thf.x, zf4.y*sxf.y+txf.y + hf4.y*shf.y+thf.y,
                        zf4.z*sxf.z+txf.z + hf4.z*shf.z+thf.z, zf4.w*sxf.w+txf.w + hf4.w*shf.w+thf.w };
        float zi[4] = { zi4.x*sxi.x+txi.x + hi4.x*shi.x+thi.x, zi4.y*sxi.y+txi.y + hi4.y*shi.y+thi.y,
                        zi4.z*sxi.z+txi.z + hi4.z*shi.z+thi.z, zi4.w*sxi.w+txi.w + hi4.w*shi.w+thi.w };
        float zo[4] = { zo4.x*sxo.x+txo.x + ho4.x*sho.x+tho.x, zo4.y*sxo.y+txo.y + ho4.y*sho.y+tho.y,
                        zo4.z*sxo.z+txo.z + ho4.z*sho.z+tho.z, zo4.w*sxo.w+txo.w + ho4.w*sho.w+tho.w };
        float zg[4] = { zg4.x*sxg.x+txg.x + hg4.x*shg.x+thg.x, zg4.y*sxg.y+txg.y + hg4.y*shg.y+thg.y,
                        zg4.z*sxg.z+txg.z + hg4.z*shg.z+thg.z, zg4.w*sxg.w+txg.w + hg4.w*shg.w+thg.w };
        float cpv[4] = { cp.x, cp.y, cp.z, cp.w };
#pragma unroll
        for (int i = 0; i < 4; i++) {
            c[i] = sigm(zf[i]) * cpv[i] + sigm(zi[i]) * tanhf(zg[i]);
            h[i] = sigm(zo[i]) * tanhf(c[i]);
        }
    }
    ((float4*)hOut)[((size_t)b << 7) + jv] = make_float4(h[0], h[1], h[2], h[3]);
    ((float4*)cOut)[((size_t)b << 7) + jv] = make_float4(c[0], c[1], c[2], c[3]);
    // permuted tf32 export: j0 = jv*4; within its 8-group, w = j&7:
    // w=0..3 -> p=0,2,4,6 ; w=4..7 -> p=1,3,5,7
    int j0 = jv << 2;
    int gbase = ((size_t)0, (j0 & ~7));
    int p0 = (j0 & 4) ? 1 : 0;
    float* dst = hT + ((size_t)b << 9) + gbase;
#pragma unroll
    for (int i = 0; i < 4; i++) dst[p0 + 2 * i] = tf(h[i]);
}

// ---------------- launch -------------------------------------------------------
extern "C" void kernel_launch(void* const* d_in, const int* in_sizes, int n_in,
                              void* d_out, int out_size) {
    const float* x   = (const float*)d_in[0];
    const float* y   = (const float*)d_in[1];
    const float* h0  = (const float*)d_in[2];
    const float* c0  = (const float*)d_in[3];
    const float* Wx0 = (const float*)d_in[4];
    const float* Wh0 = (const float*)d_in[5];
    const float* gx0 = (const float*)d_in[6];
    const float* bx0 = (const float*)d_in[7];
    const float* gh0 = (const float*)d_in[8];
    const float* bh0 = (const float*)d_in[9];
    const float* Wx1 = (const float*)d_in[10];
    const float* Wh1 = (const float*)d_in[11];
    const float* gx1 = (const float*)d_in[12];
    const float* bx1 = (const float*)d_in[13];
    const float* gh1 = (const float*)d_in[14];
    const float* bh1 = (const float*)d_in[15];
    const float* Wo  = (const float*)d_in[16];
    const float* bo  = (const float*)d_in[17];
    float* out = (float*)d_out;

    cudaFuncSetAttribute(gemm_tn, cudaFuncAttributeMaxDynamicSharedMemorySize, 2 * STG * 4);

    float *inp, *wxp, *Zx, *Zh, *h00t, *h01t, *h1t, *h2t, *Wh0t, *Wx1t, *Wh1t, *Wot, *partX, *partH;
    cudaGetSymbolAddress((void**)&inp,   g_inp);
    cudaGetSymbolAddress((void**)&wxp,   g_WxP);
    cudaGetSymbolAddress((void**)&Zx,    g_Zx);
    cudaGetSymbolAddress((void**)&Zh,    g_Zh);
    cudaGetSymbolAddress((void**)&h00t,  g_h00t);
    cudaGetSymbolAddress((void**)&h01t,  g_h01t);
    cudaGetSymbolAddress((void**)&h1t,   g_h1t);
    cudaGetSymbolAddress((void**)&h2t,   g_h2t);
    cudaGetSymbolAddress((void**)&Wh0t,  g_Wh0t);
    cudaGetSymbolAddress((void**)&Wx1t,  g_Wx1t);
    cudaGetSymbolAddress((void**)&Wh1t,  g_Wh1t);
    cudaGetSymbolAddress((void**)&Wot,   g_Wot);
    cudaGetSymbolAddress((void**)&partX, g_partX);
    cudaGetSymbolAddress((void**)&partH, g_partH);

    // output layout: out[B,256], h1[B,512], h2[B,512], c1[B,512], c2[B,512]
    float* h1 = out + (size_t)B_SZ * OUTF;
    float* h2 = h1 + (size_t)B_SZ * H_SZ;
    float* c1 = h2 + (size_t)B_SZ * H_SZ;
    float* c2 = c1 + (size_t)B_SZ * H_SZ;
    const float* h00 = h0;
    const float* h01 = h0 + (size_t)B_SZ * H_SZ;
    const float* c00 = c0;
    const float* c01 = c0 + (size_t)B_SZ * H_SZ;

    const int BH = B_SZ * H_SZ;
    const int GH = G4 * H_SZ;

    prep_inp<<<(B_SZ * (KPAD / 8) + 255) / 256, 256>>>(x, y);
    prep_wx<<<(G4 * (KPAD / 8) + 255) / 256, 256>>>(Wx0);
    conv_perm<<<(BH / 8 + 255) / 256, 256>>>(h00t, h00, BH / 8);
    conv_perm<<<(BH / 8 + 255) / 256, 256>>>(h01t, h01, BH / 8);
    conv_perm<<<(GH / 8 + 255) / 256, 256>>>(Wh0t, Wh0, GH / 8);
    conv_perm<<<(GH / 8 + 255) / 256, 256>>>(Wx1t, Wx1, GH / 8);
    conv_perm<<<(GH / 8 + 255) / 256, 256>>>(Wh1t, Wh1, GH / 8);
    conv_perm<<<(OUTF * H_SZ / 8 + 255) / 256, 256>>>(Wot, Wo, OUTF * H_SZ / 8);

    dim3 gg(G4 / BN, B_SZ / BM);     // 16 x 128
    dim3 go(OUTF / BN, B_SZ / BM);   // 2 x 128
    size_t smem = 2 * STG * 4;       // 64 KB

    // layer 0
    gemm_tn<<<gg, 256, smem>>>(Zx, inp,  KPAD, wxp,  KPAD, G4, KPAD, nullptr, partX);
    gemm_tn<<<gg, 256, smem>>>(Zh, h00t, H_SZ, Wh0t, H_SZ, G4, H_SZ, nullptr, partH);
    stats_final<<<G4 / 256, 256>>>(gx0, bx0, gh0, bh0);
    cell_kernel<<<BH / 4 / 256, 256>>>(Zx, Zh, c00, h1, h1t, c1);

    // layer 1
    gemm_tn<<<gg, 256, smem>>>(Zx, h1t,  H_SZ, Wx1t, H_SZ, G4, H_SZ, nullptr, partX);
    gemm_tn<<<gg, 256, smem>>>(Zh, h01t, H_SZ, Wh1t, H_SZ, G4, H_SZ, nullptr, partH);
    stats_final<<<G4 / 256, 256>>>(gx1, bx1, gh1, bh1);
    cell_kernel<<<BH / 4 / 256, 256>>>(Zx, Zh, c01, h2, h2t, c2);

    // output projection
    gemm_tn<<<go, 256, smem>>>(out, h2t, H_SZ, Wot, H_SZ, OUTF, H_SZ, bo, nullptr);
}

// round 9
// speedup vs baseline: 1.0905x; 1.0905x over previous
#include <cuda_runtime.h>
#include <cstdint>
#include <math.h>

#define B_SZ 16384
#define H_SZ 512
#define G4   2048
#define OUTF 256
#define KPAD 288
#define IN0  257
#define MB   128          // row-blocks along batch = B/128

// ---------------- scratch (static device memory) ------------------------------
__device__ float g_inpPad[(size_t)B_SZ * KPAD];   // zero-padded concat(x,y)
__device__ float g_WxPad [(size_t)G4 * KPAD];     // zero-padded Wx0
__device__ float g_Zx    [(size_t)B_SZ * G4];
__device__ float g_Zh    [(size_t)B_SZ * G4];
__device__ float g_partX [(size_t)MB * G4 * 2];   // per-rowblock col (sum, sumsq)
__device__ float g_partH [(size_t)MB * G4 * 2];
__device__ float g_scX[G4], g_shX[G4], g_scH[G4], g_shH[G4];

// ---------------- helpers ------------------------------------------------------
__device__ __forceinline__ uint32_t f2tf(float f) {
    uint32_t u = __float_as_uint(f);
    uint32_t r = u + 0xFFFu + ((u >> 13) & 1u);   // RNE to tf32
    return r & 0xFFFFE000u;
}
__device__ __forceinline__ float sigm(float x) { return 1.f / (1.f + expf(-x)); }

// ---------------- prep kernels (padding only, fp32 passthrough) ----------------
__global__ void prep_inp(const float* __restrict__ x, const float* __restrict__ y,
                         float* __restrict__ o) {
    int idx = blockIdx.x * blockDim.x + threadIdx.x;   // B*KPAD
    int b = idx / KPAD, k = idx - b * KPAD;
    float v = (k < 256) ? x[(size_t)b * 256 + k] : (k == 256 ? y[b] : 0.f);
    o[idx] = v;
}
__global__ void prep_wx(const float* __restrict__ Wx, float* __restrict__ o) {
    int idx = blockIdx.x * blockDim.x + threadIdx.x;   // G4*KPAD
    int r = idx / KPAD, k = idx - r * KPAD;
    o[idx] = (k < IN0) ? Wx[(size_t)r * IN0 + k] : 0.f;
}

// ---------------- tf32 tensor-core GEMM: C[M,N] = A[M,K] * W[N,K]^T (+bias) ---
// block tile 128x128, BK=32, 8 warps (4x2), warp tile 32x64, mma m16n8k8 tf32
// (round-2 proven config) + fused BN-statistics epilogue.
constexpr int BM = 128, BN = 128, BK = 32, PADX = 4;

__global__ __launch_bounds__(256, 2) void gemm_tn(
    float* __restrict__ C, const float* __restrict__ A, int lda,
    const float* __restrict__ W, int ldw, int M, int N, int K,
    const float* __restrict__ bias, float* __restrict__ part)
{
    __shared__ uint32_t As[BM][BK + PADX];
    __shared__ uint32_t Ws[BN][BK + PADX];
    const int tid  = threadIdx.x;
    const int lane = tid & 31, warp = tid >> 5;
    const int g    = lane >> 2, tg = lane & 3;       // groupID, threadID_in_group
    const int wm   = warp >> 1, wn = warp & 1;
    const int mW   = wm * 32, nW = wn * 64;
    const int bM   = blockIdx.y * BM, bN = blockIdx.x * BN;

    float acc[2][8][4];
#pragma unroll
    for (int i = 0; i < 2; i++)
#pragma unroll
        for (int j = 0; j < 8; j++)
#pragma unroll
            for (int r = 0; r < 4; r++) acc[i][j][r] = 0.f;

    for (int k0 = 0; k0 < K; k0 += BK) {
        float4 av[4], wv[4];
#pragma unroll
        for (int i = 0; i < 4; i++) {
            int idx = tid + i * 256;
            int r = idx >> 3, c4 = idx & 7;          // 8 float4 per 32-float row
            av[i] = *(const float4*)(A + (size_t)(bM + r) * lda + (k0 + c4 * 4));
            wv[i] = *(const float4*)(W + (size_t)(bN + r) * ldw + (k0 + c4 * 4));
        }
        __syncthreads();   // previous iteration's compute done before overwrite
#pragma unroll
        for (int i = 0; i < 4; i++) {
            int idx = tid + i * 256;
            int r = idx >> 3, c = (idx & 7) * 4;
            As[r][c + 0] = f2tf(av[i].x); As[r][c + 1] = f2tf(av[i].y);
            As[r][c + 2] = f2tf(av[i].z); As[r][c + 3] = f2tf(av[i].w);
            Ws[r][c + 0] = f2tf(wv[i].x); Ws[r][c + 1] = f2tf(wv[i].y);
            Ws[r][c + 2] = f2tf(wv[i].z); Ws[r][c + 3] = f2tf(wv[i].w);
        }
        __syncthreads();
#pragma unroll
        for (int kk = 0; kk < BK; kk += 8) {
            uint32_t a[2][4], b[8][2];
#pragma unroll
            for (int mt = 0; mt < 2; mt++) {
                int r0 = mW + mt * 16 + g;
                a[mt][0] = As[r0    ][kk + tg];
                a[mt][1] = As[r0 + 8][kk + tg];
                a[mt][2] = As[r0    ][kk + tg + 4];
                a[mt][3] = As[r0 + 8][kk + tg + 4];
            }
#pragma unroll
            for (int nt = 0; nt < 8; nt++) {
                int rn = nW + nt * 8 + g;
                b[nt][0] = Ws[rn][kk + tg];
                b[nt][1] = Ws[rn][kk + tg + 4];
            }
#pragma unroll
            for (int mt = 0; mt < 2; mt++)
#pragma unroll
                for (int nt = 0; nt < 8; nt++)
                    asm volatile(
                        "mma.sync.aligned.m16n8k8.row.col.f32.tf32.tf32.f32 "
                        "{%0,%1,%2,%3},{%4,%5,%6,%7},{%8,%9},{%0,%1,%2,%3};\n"
                        : "+f"(acc[mt][nt][0]), "+f"(acc[mt][nt][1]),
                          "+f"(acc[mt][nt][2]), "+f"(acc[mt][nt][3])
                        : "r"(a[mt][0]), "r"(a[mt][1]), "r"(a[mt][2]), "r"(a[mt][3]),
                          "r"(b[nt][0]), "r"(b[nt][1]));
        }
    }

    // ---- C-tile writeback (registers only; no smem dependency) ----
#pragma unroll
    for (int mt = 0; mt < 2; mt++) {
        int r0 = bM + mW + mt * 16 + g;
#pragma unroll
        for (int nt = 0; nt < 8; nt++) {
            int c = bN + nW + nt * 8 + 2 * tg;
            float b0 = 0.f, b1 = 0.f;
            if (bias) { b0 = bias[c]; b1 = bias[c + 1]; }
            *(float2*)(C + (size_t)r0 * N + c)       = make_float2(acc[mt][nt][0] + b0, acc[mt][nt][1] + b1);
            *(float2*)(C + (size_t)(r0 + 8) * N + c) = make_float2(acc[mt][nt][2] + b0, acc[mt][nt][3] + b1);
        }
    }

    // ---- fused BN statistics: per-block column (sum, sumsq) partials ----
    if (part) {
        __syncthreads();                       // all warps done reading As/Ws
        float* psm = (float*)&As[0][0];        // reuse smem: [4 wm][128 col][2]
#pragma unroll
        for (int nt = 0; nt < 8; nt++) {
            float s0 = 0.f, q0 = 0.f, s1 = 0.f, q1 = 0.f;
#pragma unroll
            for (int mt = 0; mt < 2; mt++) {
                float v0 = acc[mt][nt][0], v2 = acc[mt][nt][2];
                float v1 = acc[mt][nt][1], v3 = acc[mt][nt][3];
                s0 += v0 + v2; q0 += v0 * v0 + v2 * v2;
                s1 += v1 + v3; q1 += v1 * v1 + v3 * v3;
            }
            // reduce over g (8 lanes: stride 16, 8, 4 in lane space)
#pragma unroll
            for (int off = 16; off >= 4; off >>= 1) {
                s0 += __shfl_xor_sync(0xFFFFFFFFu, s0, off);
                q0 += __shfl_xor_sync(0xFFFFFFFFu, q0, off);
                s1 += __shfl_xor_sync(0xFFFFFFFFu, s1, off);
                q1 += __shfl_xor_sync(0xFFFFFFFFu, q1, off);
            }
            if (g == 0) {
                int col = nW + nt * 8 + 2 * tg;       // 0..127 within block
                psm[(wm * 128 + col) * 2 + 0]     = s0;
                psm[(wm * 128 + col) * 2 + 1]     = q0;
                psm[(wm * 128 + col + 1) * 2 + 0] = s1;
                psm[(wm * 128 + col + 1) * 2 + 1] = q1;
            }
        }
        __syncthreads();
        {   // 256 threads: fold 4 wm quarters -> 128 cols x {s,q}
            int col = tid >> 1, sq = tid & 1;
            float v = psm[(col) * 2 + sq] + psm[(128 + col) * 2 + sq]
                    + psm[(256 + col) * 2 + sq] + psm[(384 + col) * 2 + sq];
            part[((size_t)blockIdx.y * N + bN + col) * 2 + sq] = v;
        }
    }
}

// ---------------- fold partials into BN affine scale/shift ---------------------
__global__ void stats_final(const float* __restrict__ gx, const float* __restrict__ bx,
                            const float* __restrict__ gh, const float* __restrict__ bh) {
    int j = blockIdx.x * blockDim.x + threadIdx.x;     // 2048
    float sx = 0.f, qx = 0.f, sh = 0.f, qh = 0.f;
    for (int rb = 0; rb < MB; rb++) {
        size_t o = ((size_t)rb * G4 + j) * 2;
        sx += g_partX[o]; qx += g_partX[o + 1];
        sh += g_partH[o]; qh += g_partH[o + 1];
    }
    const float invB = 1.f / (float)B_SZ;
    float mx = sx * invB, vx = qx * invB - mx * mx;
    float ax = gx[j] * rsqrtf(vx + 1e-5f);
    g_scX[j] = ax; g_shX[j] = bx[j] - mx * ax;
    float mh = sh * invB, vh = qh * invB - mh * mh;
    float ah = gh[j] * rsqrtf(vh + 1e-5f);
    g_scH[j] = ah; g_shH[j] = bh[j] - mh * ah;
}

// ---------------- fused BN + LSTM cell (float4 vectorized) ---------------------
__global__ void cell_kernel(const float* __restrict__ Zx, const float* __restrict__ Zh,
                            const float* __restrict__ cPrev,
                            float* __restrict__ hOut, float* __restrict__ cOut) {
    int t = blockIdx.x * blockDim.x + threadIdx.x;     // B*128 threads
    int jv = t & 127, b = t >> 7;                      // jv: float4 index in 512
    size_t base4 = ((size_t)b << 9) + jv;              // float4 units of 2048-row
    const float4* zx = (const float4*)Zx;
    const float4* zh = (const float4*)Zh;
    float4 zf4 = zx[base4      ], hf4 = zh[base4      ];
    float4 zi4 = zx[base4 + 128], hi4 = zh[base4 + 128];
    float4 zo4 = zx[base4 + 256], ho4 = zh[base4 + 256];
    float4 zg4 = zx[base4 + 384], hg4 = zh[base4 + 384];
    const float4* scX = (const float4*)g_scX; const float4* shX = (const float4*)g_shX;
    const float4* scH = (const float4*)g_scH; const float4* shH = (const float4*)g_shH;
    float4 sxf = scX[jv], txf = shX[jv], shf = scH[jv], thf = shH[jv];
    float4 sxi = scX[jv + 128], txi = shX[jv + 128], shi = scH[jv + 128], thi = shH[jv + 128];
    float4 sxo = scX[jv + 256], txo = shX[jv + 256], sho = scH[jv + 256], tho = shH[jv + 256];
    float4 sxg = scX[jv + 384], txg = shX[jv + 384], shg = scH[jv + 384], thg = shH[jv + 384];
    float4 cp = ((const float4*)cPrev)[((size_t)b << 7) + jv];

    float zf[4] = { zf4.x*sxf.x+txf.x + hf4.x*shf.x+thf.x, zf4.y*sxf.y+txf.y + hf4.y*shf.y+thf.y,
                    zf4.z*sxf.z+txf.z + hf4.z*shf.z+thf.z, zf4.w*sxf.w+txf.w + hf4.w*shf.w+thf.w };
    float zi[4] = { zi4.x*sxi.x+txi.x + hi4.x*shi.x+thi.x, zi4.y*sxi.y+txi.y + hi4.y*shi.y+thi.y,
                    zi4.z*sxi.z+txi.z + hi4.z*shi.z+thi.z, zi4.w*sxi.w+txi.w + hi4.w*shi.w+thi.w };
    float zo[4] = { zo4.x*sxo.x+txo.x + ho4.x*sho.x+tho.x, zo4.y*sxo.y+txo.y + ho4.y*sho.y+tho.y,
                    zo4.z*sxo.z+txo.z + ho4.z*sho.z+tho.z, zo4.w*sxo.w+txo.w + ho4.w*sho.w+tho.w };
    float zg[4] = { zg4.x*sxg.x+txg.x + hg4.x*shg.x+thg.x, zg4.y*sxg.y+txg.y + hg4.y*shg.y+thg.y,
                    zg4.z*sxg.z+txg.z + hg4.z*shg.z+thg.z, zg4.w*sxg.w+txg.w + hg4.w*shg.w+thg.w };
    float cpv[4] = { cp.x, cp.y, cp.z, cp.w };
    float h[4], c[4];
#pragma unroll
    for (int i = 0; i < 4; i++) {
        c[i] = sigm(zf[i]) * cpv[i] + sigm(zi[i]) * tanhf(zg[i]);
        h[i] = sigm(zo[i]) * tanhf(c[i]);
    }
    ((float4*)hOut)[((size_t)b << 7) + jv] = make_float4(h[0], h[1], h[2], h[3]);
    ((float4*)cOut)[((size_t)b << 7) + jv] = make_float4(c[0], c[1], c[2], c[3]);
}

// ---------------- launch -------------------------------------------------------
extern "C" void kernel_launch(void* const* d_in, const int* in_sizes, int n_in,
                              void* d_out, int out_size) {
    const float* x   = (const float*)d_in[0];
    const float* y   = (const float*)d_in[1];
    const float* h0  = (const float*)d_in[2];
    const float* c0  = (const float*)d_in[3];
    const float* Wx0 = (const float*)d_in[4];
    const float* Wh0 = (const float*)d_in[5];
    const float* gx0 = (const float*)d_in[6];
    const float* bx0 = (const float*)d_in[7];
    const float* gh0 = (const float*)d_in[8];
    const float* bh0 = (const float*)d_in[9];
    const float* Wx1 = (const float*)d_in[10];
    const float* Wh1 = (const float*)d_in[11];
    const float* gx1 = (const float*)d_in[12];
    const float* bx1 = (const float*)d_in[13];
    const float* gh1 = (const float*)d_in[14];
    const float* bh1 = (const float*)d_in[15];
    const float* Wo  = (const float*)d_in[16];
    const float* bo  = (const float*)d_in[17];
    float* out = (float*)d_out;

    float *inp, *wxp, *Zx, *Zh, *partX, *partH;
    cudaGetSymbolAddress((void**)&inp,   g_inpPad);
    cudaGetSymbolAddress((void**)&wxp,   g_WxPad);
    cudaGetSymbolAddress((void**)&Zx,    g_Zx);
    cudaGetSymbolAddress((void**)&Zh,    g_Zh);
    cudaGetSymbolAddress((void**)&partX, g_partX);
    cudaGetSymbolAddress((void**)&partH, g_partH);

    // output layout: out[B,256], h1[B,512], h2[B,512], c1[B,512], c2[B,512]
    float* h1 = out + (size_t)B_SZ * OUTF;
    float* h2 = h1 + (size_t)B_SZ * H_SZ;
    float* c1 = h2 + (size_t)B_SZ * H_SZ;
    float* c2 = c1 + (size_t)B_SZ * H_SZ;
    const float* h00 = h0;
    const float* h01 = h0 + (size_t)B_SZ * H_SZ;
    const float* c00 = c0;
    const float* c01 = c0 + (size_t)B_SZ * H_SZ;

    const int BH = B_SZ * H_SZ;

    prep_inp<<<(B_SZ * KPAD) / 256, 256>>>(x, y, inp);
    prep_wx<<<(G4 * KPAD) / 256, 256>>>(Wx0, wxp);

    dim3 gg(G4 / BN, B_SZ / BM);     // 16 x 128
    dim3 go(OUTF / BN, B_SZ / BM);   // 2 x 128

    // layer 0
    gemm_tn<<<gg, 256>>>(Zx, inp, KPAD, wxp, KPAD, B_SZ, G4, KPAD, nullptr, partX);
    gemm_tn<<<gg, 256>>>(Zh, h00, H_SZ, Wh0, H_SZ, B_SZ, G4, H_SZ, nullptr, partH);
    stats_final<<<G4 / 256, 256>>>(gx0, bx0, gh0, bh0);
    cell_kernel<<<BH / 4 / 256, 256>>>(Zx, Zh, c00, h1, c1);

    // layer 1
    gemm_tn<<<gg, 256>>>(Zx, h1, H_SZ, Wx1, H_SZ, B_SZ, G4, H_SZ, nullptr, partX);
    gemm_tn<<<gg, 256>>>(Zh, h01, H_SZ, Wh1, H_SZ, B_SZ, G4, H_SZ, nullptr, partH);
    stats_final<<<G4 / 256, 256>>>(gx1, bx1, gh1, bh1);
    cell_kernel<<<BH / 4 / 256, 256>>>(Zx, Zh, c01, h2, c2);

    // output projection (no stats)
    gemm_tn<<<go, 256>>>(out, h2, H_SZ, Wo, H_SZ, B_SZ, OUTF, H_SZ, bo, nullptr);
}